// round 17
// baseline (speedup 1.0000x reference)
#include <cuda_runtime.h>
#include <cstdint>

// ---------------------------------------------------------------------------
// out[b,o,y,x] = sum_{t,i} softmax(a_b)[t] * W[o,i,t] * X[b,i,y+dy,x+dx]
// Implicit GEMM per batch: M=256, N=4096 (32 tiles of 128), K=2304, K-tile 32.
// mma.sync.m16n8k8 TF32.  Same CTA tile / smem / ring protocol as R16, but
// R17: 512 threads, 16 warps, warp tile 64x32 (acc=64 regs) -> 4 warps/SMSP
// for real latency hiding.  Consume loop restructured to stay under the
// 128-reg cap: load B-quads for half the K-step, then per-ks A frags.
// full barrier: 512 cp-arrives; free barrier: 16 warp-arrives.
// ---------------------------------------------------------------------------

#define BM   256
#define BN   128
#define BK   32
#define NKT  72
#define NST  4
#define NTHR 512
#define A_BYTES 32768                 // 2048 uint4: [widm4][mi4][ks4][lane32]
#define B_BYTES 16384                 // 128 rows x 128 B, permuted-k + XOR quads
#define STAGE_BYTES (A_BYTES + B_BYTES)
#define HDR  128
#define SMEM_TOTAL (HDR + NST*STAGE_BYTES)   // 196736 B

#define OFF_FULL 0                    // 4 mbarriers x 8 B
#define OFF_FREE 32                   // 4 mbarriers x 8 B

// Scratch (__device__ globals: allocation-free rule)
__device__ float g_Wf[NKT*8192];            // prefragged RAW fp32 W, 2.36 MB
__device__ float g_WfB[64ull*NKT*8192];     // per-batch masked tf32 frags, 151 MB
__device__ float g_Xt[64ull*4096*256];      // NHWC tf32, permuted-k, 256 MB
__device__ float g_mask[64*9];

__device__ __forceinline__ unsigned smem_u32(const void* p){
    return (unsigned)__cvta_generic_to_shared(p);
}
__device__ __forceinline__ void mbar_init(unsigned a, unsigned cnt){
    asm volatile("mbarrier.init.shared.b64 [%0], %1;" :: "r"(a), "r"(cnt) : "memory");
}
__device__ __forceinline__ void mbar_arrive(unsigned a){
    asm volatile("mbarrier.arrive.shared.b64 _, [%0];" :: "r"(a) : "memory");
}
__device__ __forceinline__ void cp_arrive_noinc(unsigned a){
    asm volatile("cp.async.mbarrier.arrive.noinc.shared.b64 [%0];" :: "r"(a) : "memory");
}
__device__ __forceinline__ void mbar_wait(unsigned a, unsigned ph){
    unsigned done;
    asm volatile("{\n\t.reg .pred p;\n\t"
        "mbarrier.try_wait.parity.acquire.cta.shared::cta.b64 p, [%1], %2;\n\t"
        "selp.b32 %0, 1, 0, p;\n\t}" : "=r"(done) : "r"(a), "r"(ph) : "memory");
    if (!done){
        asm volatile("{\n\t.reg .pred P1;\n\tW%=:\n\t"
            "mbarrier.try_wait.parity.acquire.cta.shared::cta.b64 P1, [%0], %1, 0x989680;\n\t"
            "@P1 bra.uni D%=;\n\tbra.uni W%=;\n\tD%=:\n\t}"
            :: "r"(a), "r"(ph) : "memory");
    }
}
// relaxed: ONLY for producer free-waits (post-wait accesses are cp.async writes)
__device__ __forceinline__ void mbar_wait_relaxed(unsigned a, unsigned ph){
    unsigned done;
    asm volatile("{\n\t.reg .pred p;\n\t"
        "mbarrier.try_wait.parity.relaxed.cta.shared::cta.b64 p, [%1], %2;\n\t"
        "selp.b32 %0, 1, 0, p;\n\t}" : "=r"(done) : "r"(a), "r"(ph) : "memory");
    if (!done){
        asm volatile("{\n\t.reg .pred P1;\n\tW%=:\n\t"
            "mbarrier.try_wait.parity.relaxed.cta.shared::cta.b64 P1, [%0], %1, 0x989680;\n\t"
            "@P1 bra.uni D%=;\n\tbra.uni W%=;\n\tD%=:\n\t}"
            :: "r"(a), "r"(ph) : "memory");
    }
}

// ---------------------------------------------------------------------------
__global__ void prep_mask_kernel(const float* __restrict__ act){
    int b = blockIdx.x * blockDim.x + threadIdx.x;
    if (b < 64){
        float v[9]; float mx = -3.4e38f;
        #pragma unroll
        for (int t = 0; t < 9; t++){ v[t] = act[b*9+t]; mx = fmaxf(mx, v[t]); }
        float s = 0.f;
        #pragma unroll
        for (int t = 0; t < 9; t++){ v[t] = expf(v[t]-mx); s += v[t]; }
        float inv = 1.f/s;
        #pragma unroll
        for (int t = 0; t < 9; t++) g_mask[b*9+t] = v[t]*inv;
    }
}

// W[o][i][t] -> fragment-order RAW fp32
__global__ void prep_wf_kernel(const float* __restrict__ w){
    int idx = blockIdx.x * blockDim.x + threadIdx.x;     // 147456 float4
    if (idx >= NKT*2048) return;
    int lane =  idx        & 31;
    int ks   = (idx >> 5)  & 3;
    int mi   = (idx >> 7)  & 3;
    int widm = (idx >> 9)  & 3;
    int kt   =  idx >> 11;
    int g = lane >> 2, tig = lane & 3;
    int m  = widm*64 + mi*16 + g;
    int t  = kt >> 3;
    int i0 = (kt & 7) * 32;
    int ia = i0 + ks*8 + tig;
    int ib = ia + 4;
    float4 v;
    v.x = w[(size_t)m    *2304 + ia*9 + t];
    v.y = w[(size_t)(m+8)*2304 + ia*9 + t];
    v.z = w[(size_t)m    *2304 + ib*9 + t];
    v.w = w[(size_t)(m+8)*2304 + ib*9 + t];
    reinterpret_cast<float4*>(g_Wf)[idx] = v;
}

// g_Wf (raw) x mask[b][t] -> g_WfB[b], tf32 (single rounding of m*w)
__global__ void prep_wfb_kernel(){
    int idx = blockIdx.x * blockDim.x + threadIdx.x;     // 0..147455
    int b   = blockIdx.y;
    int t   = idx >> 14;
    float mt = g_mask[b*9 + t];
    float4 v = reinterpret_cast<const float4*>(g_Wf)[idx];
    unsigned u0,u1,u2,u3;
    asm("cvt.rna.tf32.f32 %0, %1;" : "=r"(u0) : "f"(v.x*mt));
    asm("cvt.rna.tf32.f32 %0, %1;" : "=r"(u1) : "f"(v.y*mt));
    asm("cvt.rna.tf32.f32 %0, %1;" : "=r"(u2) : "f"(v.z*mt));
    asm("cvt.rna.tf32.f32 %0, %1;" : "=r"(u3) : "f"(v.w*mt));
    reinterpret_cast<uint4*>(g_WfB)[(size_t)b*(NKT*2048) + idx] =
        make_uint4(u0,u1,u2,u3);
}

// X[b][c][p] -> g_Xt[b][p][perm(c)], tf32.  perm within each 32-ch group:
// pos(kl) = (kl&3)*8 + ((kl>>3)&3)*2 + ((kl>>2)&1)
__global__ void prep_x_kernel(const float* __restrict__ inp){
    __shared__ float tile[32][33];
    int b = blockIdx.z, p0 = blockIdx.x*32, c0 = blockIdx.y*32;
    int tx = threadIdx.x, ty = threadIdx.y;              // (32, 8)
    const float* src = inp + (((size_t)b*256 + c0)*4096 + p0);
    #pragma unroll
    for (int r = 0; r < 4; r++)
        tile[ty + 8*r][tx] = src[(size_t)(ty + 8*r)*4096 + tx];
    __syncthreads();
    int pos = (tx&3)*8 + ((tx>>3)&3)*2 + ((tx>>2)&1);
    unsigned* dst = reinterpret_cast<unsigned*>(g_Xt) + (((size_t)b*4096 + p0)*256 + c0);
    #pragma unroll
    for (int r = 0; r < 4; r++){
        unsigned u;
        asm("cvt.rna.tf32.f32 %0, %1;" : "=r"(u) : "f"(tile[tx][ty + 8*r]));
        dst[(size_t)(ty + 8*r)*256 + pos] = u;
    }
}

// ---------------------------------------------------------------------------
__global__ void __launch_bounds__(NTHR, 1) masc_conv_kernel(float* __restrict__ out)
{
    extern __shared__ char smem[];
    const unsigned sb = smem_u32(smem);
    const int tid  = threadIdx.x;
    const int lane = tid & 31;
    const int wid  = tid >> 5;          // 0..15
    const int widm = wid >> 2;          // 4 warps in M (64 rows each)
    const int wn   = (wid & 3) * 32;    // 4 warps in N (32 cols each)
    const int g    = lane >> 2;
    const int tig  = lane & 3;
    const int b    = blockIdx.z;
    const int p0   = blockIdx.x * BN;
    // 4 warps per SMSP (wid&3 = SMSP); alternate produce position so
    // SMSP-mates interleave LDS bursts with MMA bursts.
    const bool prodFirst = ((wid >> 2) & 1) == 0;

    const float* xB = g_Xt + (size_t)b*4096*256;
    const uint4* aB = reinterpret_cast<const uint4*>(g_WfB) + (size_t)b*(NKT*2048);

    // B staging role: row n = tid&127, 2 of 8 16B segments
    const int bn   = tid & 127;
    const int bs0  = (tid >> 7) * 2;

    // pipeline mbarriers: full = 512 cp-arrives, free = 16 warp-arrives
    if (tid < NST)                 mbar_init(sb + OFF_FULL + tid*8, NTHR);
    else if (tid >= 32 && tid < 32+NST) mbar_init(sb + OFF_FREE + (tid-32)*8, 16);
    asm volatile("fence.proxy.async.shared::cta;" ::: "memory");
    __syncthreads();

    float acc[4][4][4];
    #pragma unroll
    for (int mi = 0; mi < 4; mi++)
        #pragma unroll
        for (int ni = 0; ni < 4; ni++)
            #pragma unroll
            for (int r = 0; r < 4; r++) acc[mi][ni][r] = 0.f;

    // ---- stage one K-tile into slot s (512 threads) ----
    auto stage = [&](int kt, int s){
        const unsigned stg = sb + HDR + s*STAGE_BYTES;
        const uint4* srcA = aB + kt*2048;
        #pragma unroll
        for (int q = 0; q < 4; q++){
            int j = tid + NTHR*q;
            asm volatile("cp.async.cg.shared.global [%0], [%1], 16;\n"
                         :: "r"(stg + j*16), "l"(srcA + j));
        }
        const int t  = kt >> 3;
        const int i0 = (kt & 7) * 32;
        const int dy = t/3 - 1, dx = t%3 - 1;
        const int p  = p0 + bn;
        const int y  = (p >> 6) + dy;
        const int x  = (p & 63) + dx;
        const bool valid = ((unsigned)y < 64u) & ((unsigned)x < 64u);
        const float* srow = xB + ((size_t)(valid ? (y*64 + x) : 0)*256 + i0);
        const int sz = valid ? 16 : 0;
        const unsigned rowDst = stg + A_BYTES + bn*128;
        #pragma unroll
        for (int q = 0; q < 2; q++){
            int sgi = bs0 + q;
            unsigned dst = rowDst + ((sgi ^ (bn & 7)) * 16);
            asm volatile("cp.async.cg.shared.global [%0], [%1], 16, %2;\n"
                         :: "r"(dst), "l"(srow + sgi*4), "r"(sz));
        }
        cp_arrive_noinc(sb + OFF_FULL + s*8);   // full[s] when copies land
    };

    // produce canonical slot kt+3 (with backpressure wait)
    auto produce = [&](int kt){
        const int kn = kt + 3;
        if (kn < NKT){
            const int sn = kn & 3, rn = kn >> 2;
            if (rn > 0) mbar_wait_relaxed(sb + OFF_FREE + sn*8, (rn - 1) & 1);
            stage(kn, sn);
        }
    };

    // consume slot kt: full-wait, frags, 64 HMMA, free-arrive.
    // Register discipline: B quads for one K-half (16 regs) + per-ks A frags
    // (16 regs) live at a time -> fits the 128-reg cap with acc=64.
    auto consume = [&](int kt){
        const int s = kt & 3;
        mbar_wait(sb + OFF_FULL + s*8, (kt >> 2) & 1);

        const char* stg = smem + HDR + s*STAGE_BYTES;
        const uint4* sA = reinterpret_cast<const uint4*>(stg);
        const char*  sB = stg + A_BYTES;

        #pragma unroll
        for (int h = 0; h < 2; h++){                 // K-half: ks = 2h, 2h+1
            // B quads: quad index (2*tig + h-selected) — qa covers ks pair
            const unsigned qa = ((2*tig + h) ^ g) * 16;
            uint4 bq[4];
            #pragma unroll
            for (int ni = 0; ni < 4; ni++)
                bq[ni] = *reinterpret_cast<const uint4*>(
                             sB + (wn + ni*8 + g)*128 + qa);
            // NOTE quad layout: qa(h=0) = {b0(ks0),b1(ks0),b0(ks1),b1(ks1)}
            //                   qa(h=1) = {b0(ks2),b1(ks2),b0(ks3),b1(ks3)}
            #pragma unroll
            for (int ksl = 0; ksl < 2; ksl++){
                const int ks = h*2 + ksl;
                uint4 af[4];
                #pragma unroll
                for (int mi = 0; mi < 4; mi++)
                    af[mi] = sA[((widm*4 + mi)*4 + ks)*32 + lane];
                #pragma unroll
                for (int mi = 0; mi < 4; mi++)
                    #pragma unroll
                    for (int ni = 0; ni < 4; ni++){
                        unsigned b0 = ksl ? bq[ni].z : bq[ni].x;
                        unsigned b1 = ksl ? bq[ni].w : bq[ni].y;
                        asm volatile(
                            "mma.sync.aligned.m16n8k8.row.col.f32.tf32.tf32.f32 "
                            "{%0,%1,%2,%3}, {%4,%5,%6,%7}, {%8,%9}, {%0,%1,%2,%3};\n"
                            : "+f"(acc[mi][ni][0]), "+f"(acc[mi][ni][1]),
                              "+f"(acc[mi][ni][2]), "+f"(acc[mi][ni][3])
                            : "r"(af[mi].x), "r"(af[mi].y),
                              "r"(af[mi].z), "r"(af[mi].w),
                              "r"(b0), "r"(b1));
                    }
            }
        }

        if (lane == 0) mbar_arrive(sb + OFF_FREE + s*8);
    };

    // Wait: quad layout check.  uint4 at qa(h) = quads (2tig+h)^g... with
    // permuted channels pos = tig*8 + ks*2 + hbit, thread reads 32B starting
    // at byte ((2*tig + h_sel)^g)*16?  The R12-proven mapping: qa0=(2tig)^g
    // covers ks0/ks1, qa1=(2tig+1)^g covers ks2/ks3.  So h selects qa0/qa1.

    // ---- prologue: fill slots 0..2 (round 0, no free-wait) ----
    stage(0, 0);
    stage(1, 1);
    stage(2, 2);

    // ---- main loop: canonical order, staggered produce position ----
    if (prodFirst){
        #pragma unroll 1
        for (int kt = 0; kt < NKT; kt++){ produce(kt); consume(kt); }
    } else {
        #pragma unroll 1
        for (int kt = 0; kt < NKT; kt++){ consume(kt); produce(kt); }
    }

    // ---- epilogue: c0/c1 and c2/c3 adjacent columns -> 8B stores ----
    float* outB = out + ((size_t)(b*256 + widm*64))*4096 + p0 + wn;
    #pragma unroll
    for (int mi = 0; mi < 4; mi++){
        #pragma unroll
        for (int ni = 0; ni < 4; ni++){
            int r0  = mi*16 + g;
            int col = ni*8 + 2*tig;
            float2 v0 = make_float2(acc[mi][ni][0], acc[mi][ni][1]);
            float2 v1 = make_float2(acc[mi][ni][2], acc[mi][ni][3]);
            *reinterpret_cast<float2*>(outB + (size_t)r0      *4096 + col) = v0;
            *reinterpret_cast<float2*>(outB + (size_t)(r0 + 8)*4096 + col) = v1;
        }
    }
}

// ---------------------------------------------------------------------------
extern "C" void kernel_launch(void* const* d_in, const int* in_sizes, int n_in,
                              void* d_out, int out_size)
{
    const float* inp = (const float*)d_in[0];   // [64,256,64,64] f32
    const float* act = (const float*)d_in[1];   // [64,9] f32
    const float* w   = (const float*)d_in[2];   // [256,256,3,3] f32
    float* out = (float*)d_out;

    cudaFuncSetAttribute(masc_conv_kernel,
                         cudaFuncAttributeMaxDynamicSharedMemorySize, SMEM_TOTAL);

    prep_mask_kernel<<<2, 32>>>(act);
    prep_wf_kernel<<<576, 256>>>(w);                    // 147456 float4
    prep_wfb_kernel<<<dim3(576, 64), 256>>>();          // 151 MB masked frags
    prep_x_kernel<<<dim3(128, 8, 64), dim3(32, 8)>>>(inp);
    masc_conv_kernel<<<dim3(32, 1, 64), NTHR, SMEM_TOTAL>>>(out);

    (void)in_sizes; (void)n_in; (void)out_size;
}